// round 16
// baseline (speedup 1.0000x reference)
#include <cuda_runtime.h>
#include <cuda_bf16.h>
#include <cuda_fp16.h>
#include <cstdint>

// CausalSelfAttention: B=4, T=4096, C=128, fp32 in/out.
// K1: tensorized QKV projection, fp16 2-term GEMM (x fp16 hi/lo x W fp16).
//     Outputs: Q fp16 (pre-scaled), K fp16, V fp16 (transposed).
// K2: persistent flash attention: warp-private 16-row tiles; S,PV fp16
//     single-term; masked warp-tile skip; SMSP warp-pair stagger;
//     cp.async staged Q + double-buffered K/V; split-KV queue; fused combine.

#define BB 4
#define TT 4096
#define CC 128
#define BT (BB*TT)
#define QT_N 32
#define SCALE_L2E (0.08838834764831845f * 1.4426950408889634f)

#define BQ 128
#define BKT 64
#define CH 6
#define MAXSUB 11
#define NSLICES 748     // 4 * sum_qt ceil((2qt+2)/6)
#define NCTA 148

// ---------------- scratch (device globals; no cudaMalloc) -------------------
__device__ __align__(256) __half g_q[BT*CC];                 // [t][c] fp16, *SCALE_L2E
__device__ __align__(256) __half g_k[BT*CC];                 // [t][c] fp16
__device__ __align__(256) __half g_v[BB*CC*TT];              // [b][c][t] fp16
__device__ __align__(256) float g_po[BB*QT_N*MAXSUB][BQ*CC];
__device__ __align__(256) float g_pl[BB*QT_N*MAXSUB][BQ];
__device__ int g_ctr;
__device__ int g_done[BB*QT_N];

// ---------------- helpers ---------------------------------------------------
__device__ __forceinline__ uint32_t smem_u32(const void* p) {
    uint32_t a;
    asm("{ .reg .u64 t; cvta.to.shared.u64 t, %1; cvt.u32.u64 %0, t; }"
        : "=r"(a) : "l"(p));
    return a;
}
__device__ __forceinline__ void ldm4(uint32_t* r, uint32_t a) {
    asm volatile("ldmatrix.sync.aligned.m8n8.x4.shared.b16 {%0,%1,%2,%3}, [%4];"
        : "=r"(r[0]), "=r"(r[1]), "=r"(r[2]), "=r"(r[3]) : "r"(a));
}
__device__ __forceinline__ void mma16816h(float* c, const uint32_t* a,
                                          const uint32_t* b) {
    asm("mma.sync.aligned.m16n8k16.row.col.f32.f16.f16.f32 "
        "{%0,%1,%2,%3}, {%4,%5,%6,%7}, {%8,%9}, {%0,%1,%2,%3};"
        : "+f"(c[0]), "+f"(c[1]), "+f"(c[2]), "+f"(c[3])
        : "r"(a[0]), "r"(a[1]), "r"(a[2]), "r"(a[3]), "r"(b[0]), "r"(b[1]));
}
#define CP_ASYNC16(dst, src) \
    asm volatile("cp.async.cg.shared.global [%0], [%1], 16;" \
                 :: "r"(dst), "l"(src))
#define CP_COMMIT() asm volatile("cp.async.commit_group;" ::: "memory")
#define CP_WAIT(n)  asm volatile("cp.async.wait_group %0;" :: "n"(n) : "memory")

// ---------------------------------------------------------------------------
// K1: QKV projection, fp16 2-term: y = xh*W + xl*W  (x exact to 2^-21,
// W rounded 2^-11). Epilogues: Q fp16 scaled; K fp16; V fp16 transposed.
// ---------------------------------------------------------------------------
#define PX 136
#define SMX_H 0
#define SMX_L (SMX_H + 128*PX*2)
#define SMW   (SMX_L + 128*PX*2)
#define PROJ_SMEM (SMW + 128*PX*2)      // 104448
#define PSTG 129

__global__ __launch_bounds__(256, 1) void qkv_proj_mma(
    const float* __restrict__ x,
    const float* __restrict__ Wq,
    const float* __restrict__ Wk,
    const float* __restrict__ Wv)
{
    extern __shared__ char smem[];
    const uint32_t sb = smem_u32(smem);
    const int widx = blockIdx.y;
    const float* __restrict__ W = (widx == 0) ? Wq : ((widx == 1) ? Wk : Wv);
    const int row0 = blockIdx.x * 128;
    const int tid = threadIdx.x, lane = tid & 31, wid = tid >> 5;
    const int wm = wid & 3, wn = wid >> 2;
    const int gr = lane >> 2, tc = lane & 3;

    if (blockIdx.x == 0 && widx == 0) {
        if (tid == 0) g_ctr = NCTA;
        if (tid < BB * QT_N) g_done[tid] = 0;
    }

    // x: split to fp16 hi/lo
#pragma unroll
    for (int f = tid; f < 128 * 32; f += 256) {
        const int r = f >> 5, c4 = (f & 31) * 4;
        float4 v = *(const float4*)&x[(size_t)(row0 + r) * CC + c4];
        __half2 h0 = __floats2half2_rn(v.x, v.y);
        __half2 h1 = __floats2half2_rn(v.z, v.w);
        __half2 l0 = __floats2half2_rn(v.x - __low2float(h0),
                                       v.y - __high2float(h0));
        __half2 l1 = __floats2half2_rn(v.z - __low2float(h1),
                                       v.w - __high2float(h1));
        const int o = (r * PX + c4) * 2;
        *(uint32_t*)(smem + SMX_H + o)     = *reinterpret_cast<uint32_t*>(&h0);
        *(uint32_t*)(smem + SMX_H + o + 4) = *reinterpret_cast<uint32_t*>(&h1);
        *(uint32_t*)(smem + SMX_L + o)     = *reinterpret_cast<uint32_t*>(&l0);
        *(uint32_t*)(smem + SMX_L + o + 4) = *reinterpret_cast<uint32_t*>(&l1);
    }
    // W: single fp16
#pragma unroll
    for (int f = tid; f < 128 * 32; f += 256) {
        const int d = f >> 5, c4 = (f & 31) * 4;
        float4 v = *(const float4*)&W[(size_t)d * CC + c4];
        __half2 h0 = __floats2half2_rn(v.x, v.y);
        __half2 h1 = __floats2half2_rn(v.z, v.w);
        const int o = (d * PX + c4) * 2;
        *(uint32_t*)(smem + SMW + o)     = *reinterpret_cast<uint32_t*>(&h0);
        *(uint32_t*)(smem + SMW + o + 4) = *reinterpret_cast<uint32_t*>(&h1);
    }
    __syncthreads();

    const int lr = lane & 15, lh = lane >> 4;
    const int bn = (lane & 7) + ((lane >> 4) << 3);
    const int bk8 = ((lane >> 3) & 1) << 3;
    const uint32_t aXh = sb + SMX_H + (((wm * 32 + lr) * PX) + lh * 8) * 2;
    const uint32_t aXl = aXh + (SMX_L - SMX_H);
    const uint32_t aW  = sb + SMW + (((wn * 64 + bn) * PX) + bk8) * 2;

    float acc[2][8][4];
#pragma unroll
    for (int mi = 0; mi < 2; mi++)
#pragma unroll
        for (int ni = 0; ni < 8; ni++)
#pragma unroll
            for (int e = 0; e < 4; e++) acc[mi][ni][e] = 0.0f;

#pragma unroll
    for (int ks = 0; ks < 8; ++ks) {
        uint32_t ah[2][4], al[2][4], bw[8][2];
        ldm4(ah[0], aXh + ks * 32);
        ldm4(ah[1], aXh + 16 * PX * 2 + ks * 32);
        ldm4(al[0], aXl + ks * 32);
        ldm4(al[1], aXl + 16 * PX * 2 + ks * 32);
#pragma unroll
        for (int p = 0; p < 4; p++)
            ldm4(&bw[2 * p][0], aW + p * 16 * PX * 2 + ks * 32);
#pragma unroll
        for (int mi = 0; mi < 2; mi++)
#pragma unroll
            for (int ni = 0; ni < 8; ni++) {
                mma16816h(acc[mi][ni], ah[mi], bw[ni]);
                mma16816h(acc[mi][ni], al[mi], bw[ni]);
            }
    }

    if (widx < 2) {
        // ---- Q (scaled) / K: single fp16, row-major ----
        __half* dst = (widx == 0) ? g_q : g_k;
        const float sc = (widx == 0) ? SCALE_L2E : 1.0f;
#pragma unroll
        for (int mi = 0; mi < 2; mi++)
#pragma unroll
            for (int half = 0; half < 2; half++) {
                const int row = wm * 32 + mi * 16 + gr + half * 8;
                const size_t rb = (size_t)(row0 + row) * CC;
#pragma unroll
                for (int ni = 0; ni < 8; ni++) {
                    const int col = wn * 64 + ni * 8 + tc * 2;
                    __half2 H = __floats2half2_rn(acc[mi][ni][half * 2 + 0] * sc,
                                                  acc[mi][ni][half * 2 + 1] * sc);
                    *(uint32_t*)&dst[rb + col] = *reinterpret_cast<uint32_t*>(&H);
                }
            }
    } else {
        // ---- V: stage fp32, transposed single-fp16 store ----
        __syncthreads();
        float* stg = (float*)smem;
#pragma unroll
        for (int mi = 0; mi < 2; mi++)
#pragma unroll
            for (int half = 0; half < 2; half++) {
                const int row = wm * 32 + mi * 16 + gr + half * 8;
#pragma unroll
                for (int ni = 0; ni < 8; ni++) {
                    const int col = wn * 64 + ni * 8 + tc * 2;
                    stg[row * PSTG + col]     = acc[mi][ni][half * 2 + 0];
                    stg[row * PSTG + col + 1] = acc[mi][ni][half * 2 + 1];
                }
            }
        __syncthreads();
        const int b = row0 >> 12, t0 = row0 & (TT - 1);
        __half* vv = g_v + (size_t)b * CC * TT + t0;
#pragma unroll 1
        for (int c = wid; c < 128; c += 8) {
            float v[4];
#pragma unroll
            for (int i = 0; i < 4; i++)
                v[i] = stg[(lane * 4 + i) * PSTG + c];
            __half2 h0 = __floats2half2_rn(v[0], v[1]);
            __half2 h1 = __floats2half2_rn(v[2], v[3]);
            uint2 Hp = make_uint2(*reinterpret_cast<uint32_t*>(&h0),
                                  *reinterpret_cast<uint32_t*>(&h1));
            *(uint2*)&vv[(size_t)c * TT + lane * 4] = Hp;
        }
    }
}

// ---------------------------------------------------------------------------
// K2: persistent flash attention + fused combine. Q/K/V all single fp16.
// ---------------------------------------------------------------------------
#define PQ 136
#define PK 136
#define PV 72
#define SM_Q 0
#define SM_KV (128*PQ*2)                 // 34816
#define KBUF  (64*PK*2)                  // 17408
#define OFF_K 0
#define OFF_V KBUF
#define BUFSZ (KBUF + 128*PV*2)          // 35840
#define SM_NEXT (SM_KV + 2*BUFSZ)        // +0 next, +4 flag
#define SM_INVL (SM_NEXT + 16)
#define FLASH_SMEM (SM_INVL + 128*4)

__device__ __forceinline__ void prefetch_kv(uint32_t buf, int b, int j, int tid)
{
    const __half* kk = g_k + (size_t)(b * TT + j * BKT) * CC;
#pragma unroll
    for (int u = 0; u < 4; u++) {
        const int f = tid + u * 256, r = f >> 4, c8 = (f & 15) << 3;
        CP_ASYNC16(buf + OFF_K + (r * PK + c8) * 2, kk + r * CC + c8);
    }
    const __half* vv = g_v + (size_t)b * CC * TT + j * BKT;
#pragma unroll
    for (int u = 0; u < 4; u++) {
        const int f = tid + u * 256, d = f >> 3, c8 = (f & 7) << 3;
        CP_ASYNC16(buf + OFF_V + (d * PV + c8) * 2, vv + (size_t)d * TT + c8);
    }
}

__global__ __launch_bounds__(256, 1) void flash_attn(float* __restrict__ out)
{
    extern __shared__ char smem[];
    const uint32_t sb = smem_u32(smem);
    const int tid = threadIdx.x, lane = tid & 31, wid = tid >> 5;
    const int gr = lane >> 2, tc = lane & 3;
    const int rev = (wid >> 2) & 1;      // SMSP warp-pair stagger parity

    const int lr = lane & 15, lh = lane >> 4;
    const int bn = (lane & 7) + ((lane >> 4) << 3);
    const int bk8 = ((lane >> 3) & 1) << 3;

    const uint32_t aQ = sb + SM_Q + (((wid * 16 + lr) * PQ) + lh * 8) * 2;
    const uint32_t aKrel = (bn * PK + bk8) * 2;
    const uint32_t aVrel = (bn * PV + bk8) * 2;

    const int row_a = wid * 16 + gr;
    const int row_b = row_a + 8;
    const int row_max = wid * 16 + 15;   // warp's max q row (for tile skip)
    int* s_next = (int*)(smem + SM_NEXT);
    int* s_flag = (int*)(smem + SM_NEXT + 4);

    int slice = blockIdx.x;
    while (slice < NSLICES) {
        // ---- decode slice -> (b, qt, sub, kv0, kv1, ns) ----
        int rem = slice, qt = 31, ns = 1;
#pragma unroll 1
        for (qt = 31; qt > 0; --qt) {
            ns = (2 * qt + 2 + CH - 1) / CH;
            if (rem < 4 * ns) break;
            rem -= 4 * ns;
        }
        if (qt == 0) ns = 1;
        const int b = rem & 3, sub = rem >> 2;
        const int it = 2 * qt + 2;
        const int base = it / ns, r2 = it - base * ns;
        const int kv0 = sub * base + (sub < r2 ? sub : r2);
        const int kv1 = kv0 + base + (sub < r2 ? 1 : 0);
        const int slot = (b * QT_N + qt) * MAXSUB + sub;

        // ---- prologue: cp.async Q (group 1) then KV0 (group 2) ----
        {
            const __half* qq = g_q + (size_t)(b * TT + qt * BQ) * CC;
#pragma unroll
            for (int u = 0; u < 8; u++) {
                const int f = tid + u * 256, r = f >> 4, c8 = (f & 15) << 3;
                CP_ASYNC16(sb + SM_Q + (r * PQ + c8) * 2, qq + r * CC + c8);
            }
        }
        CP_COMMIT();
        prefetch_kv(sb + SM_KV, b, kv0, tid);
        CP_COMMIT();
        CP_WAIT(1);                      // Q complete; KV0 may be in flight
        __syncthreads();                 // Q visible to all warps
        uint32_t qah[8][4];
#pragma unroll
        for (int ks = 0; ks < 8; ++ks)
            ldm4(qah[ks], aQ + ks * 32);

        float o[16][4];
#pragma unroll
        for (int ni = 0; ni < 16; ni++)
#pragma unroll
            for (int e = 0; e < 4; e++) o[ni][e] = 0.0f;
        float lsumA = 0.0f, lsumB = 0.0f;

        int cur = 0;
#pragma unroll 1
        for (int j = kv0; j < kv1; ++j, cur ^= 1) {
            __syncthreads();             // prev-buffer reads complete
            if (j + 1 < kv1) {
                prefetch_kv(sb + SM_KV + (cur ^ 1) * BUFSZ, b, j + 1, tid);
                CP_COMMIT();
                CP_WAIT(1);              // tile j complete, j+1 in flight
            } else {
                CP_WAIT(0);
            }
            __syncthreads();             // tile j visible

            const int srel = j * BKT - qt * BQ;
            if (srel > row_max) continue;    // warp-tile fully masked

            const uint32_t kb = sb + SM_KV + cur * BUFSZ;
            const uint32_t aK = kb + OFF_K + aKrel;
            const uint32_t aV = kb + OFF_V + aVrel;

            // ---- S = Q K^T (16x64), fp16 single-term (staggered traversal) ----
            float s[8][4];
#pragma unroll
            for (int ni = 0; ni < 8; ni++)
#pragma unroll
                for (int e = 0; e < 4; e++) s[ni][e] = 0.0f;

#pragma unroll
            for (int ki = 0; ki < 8; ++ki) {
                const int ks = rev ? (7 - ki) : ki;
#pragma unroll
                for (int pi = 0; pi < 4; pi++) {
                    const int p = rev ? (3 - pi) : pi;
                    uint32_t k4[4];
                    ldm4(k4, aK + p * 16 * PK * 2 + ks * 32);
                    mma16816h(s[2 * p],     qah[ks], &k4[0]);
                    mma16816h(s[2 * p + 1], qah[ks], &k4[2]);
                }
            }

            // ---- softmax -> fp16 Ph A-fragments; l over rounded Ph ----
            uint32_t ph[4][4];
            if (srel + BKT - 1 <= row_a) {
                // fully unmasked for this warp's rows: no compares
#pragma unroll
                for (int ni = 0; ni < 8; ni++) {
                    const int ksv = ni >> 1, hh = (ni & 1) * 2;
                    float p0 = exp2f(s[ni][0]);
                    float p1 = exp2f(s[ni][1]);
                    float p2 = exp2f(s[ni][2]);
                    float p3 = exp2f(s[ni][3]);
                    __half2 H0 = __floats2half2_rn(p0, p1);
                    __half2 H1 = __floats2half2_rn(p2, p3);
                    lsumA += __low2float(H0) + __high2float(H0);
                    lsumB += __low2float(H1) + __high2float(H1);
                    ph[ksv][hh]     = *reinterpret_cast<uint32_t*>(&H0);
                    ph[ksv][hh + 1] = *reinterpret_cast<uint32_t*>(&H1);
                }
            } else {
#pragma unroll
                for (int ni = 0; ni < 8; ni++) {
                    const int ksv = ni >> 1, hh = (ni & 1) * 2;
                    const int col = srel + ni * 8 + tc * 2;
                    float p0 = (col     <= row_a) ? exp2f(s[ni][0]) : 0.0f;
                    float p1 = (col + 1 <= row_a) ? exp2f(s[ni][1]) : 0.0f;
                    float p2 = (col     <= row_b) ? exp2f(s[ni][2]) : 0.0f;
                    float p3 = (col + 1 <= row_b) ? exp2f(s[ni][3]) : 0.0f;
                    __half2 H0 = __floats2half2_rn(p0, p1);
                    __half2 H1 = __floats2half2_rn(p2, p3);
                    lsumA += __low2float(H0) + __high2float(H0);
                    lsumB += __low2float(H1) + __high2float(H1);
                    ph[ksv][hh]     = *reinterpret_cast<uint32_t*>(&H0);
                    ph[ksv][hh + 1] = *reinterpret_cast<uint32_t*>(&H1);
                }
            }

            // ---- O += P V (16x128), fp16 (staggered traversal) ----
#pragma unroll
            for (int ki = 0; ki < 4; ++ki) {
                const int ksv = rev ? (3 - ki) : ki;
#pragma unroll
                for (int pi = 0; pi < 8; pi++) {
                    const int p = rev ? (7 - pi) : pi;
                    uint32_t v4[4];
                    ldm4(v4, aV + p * 16 * PV * 2 + ksv * 32);
                    mma16816h(o[2 * p],     ph[ksv], &v4[0]);
                    mma16816h(o[2 * p + 1], ph[ksv], &v4[2]);
                }
            }
        }

        // ---- slice epilogue: l reduce + partial writes ----
        lsumA += __shfl_xor_sync(0xffffffffu, lsumA, 1);
        lsumA += __shfl_xor_sync(0xffffffffu, lsumA, 2);
        lsumB += __shfl_xor_sync(0xffffffffu, lsumB, 1);
        lsumB += __shfl_xor_sync(0xffffffffu, lsumB, 2);
        if (tc == 0) {
            g_pl[slot][row_a] = lsumA;
            g_pl[slot][row_b] = lsumB;
        }
        float* po = g_po[slot];
#pragma unroll
        for (int ni = 0; ni < 16; ni++) {
            const int col = ni * 8 + tc * 2;
            *(float2*)&po[row_a * CC + col] = make_float2(o[ni][0], o[ni][1]);
            *(float2*)&po[row_b * CC + col] = make_float2(o[ni][2], o[ni][3]);
        }

        // ---- fused combine: last-arriving CTA for this (b,qt) finishes it ----
        __threadfence();
        __syncthreads();
        if (tid == 0) {
            int old = atomicAdd(&g_done[b * QT_N + qt], 1);
            *s_flag = (old == ns - 1) ? 1 : 0;
        }
        __syncthreads();
        if (*s_flag) {
            __threadfence();
            const int s0 = (b * QT_N + qt) * MAXSUB;
            float* invl = (float*)(smem + SM_INVL);
            for (int r = tid; r < 128; r += 256) {
                float ssum = 0.0f;
                for (int u = 0; u < ns; u++) ssum += g_pl[s0 + u][r];
                invl[r] = 1.0f / ssum;
            }
            __syncthreads();
            float* dst = out + (size_t)(b * TT + qt * BQ) * CC;
#pragma unroll 2
            for (int f = tid; f < BQ * CC / 4; f += 256) {
                const int row = f >> 5;
                float4 a = *(const float4*)&g_po[s0][f * 4];
                for (int u = 1; u < ns; u++) {
                    float4 v = *(const float4*)&g_po[s0 + u][f * 4];
                    a.x += v.x; a.y += v.y; a.z += v.z; a.w += v.w;
                }
                const float inv = invl[row];
                a.x *= inv; a.y *= inv; a.z *= inv; a.w *= inv;
                *(float4*)&dst[f * 4] = a;
            }
        }

        // ---- pop next slice ----
        if (tid == 0) *s_next = atomicAdd(&g_ctr, 1);
        __syncthreads();
        slice = *s_next;
    }
}

// ---------------------------------------------------------------------------
extern "C" void kernel_launch(void* const* d_in, const int* in_sizes, int n_in,
                              void* d_out, int out_size)
{
    const float* x  = (const float*)d_in[0];
    const float* Wq = (const float*)d_in[1];
    const float* Wk = (const float*)d_in[2];
    const float* Wv = (const float*)d_in[3];
    float* out = (float*)d_out;

    cudaFuncSetAttribute(flash_attn,
                         cudaFuncAttributeMaxDynamicSharedMemorySize,
                         FLASH_SMEM);
    cudaFuncSetAttribute(qkv_proj_mma,
                         cudaFuncAttributeMaxDynamicSharedMemorySize,
                         PROJ_SMEM);

    qkv_proj_mma<<<dim3(BT / 128, 3), 256, PROJ_SMEM>>>(x, Wq, Wk, Wv);
    flash_attn<<<NCTA, 256, FLASH_SMEM>>>(out);
}

// round 17
// speedup vs baseline: 2.8119x; 2.8119x over previous
#include <cuda_runtime.h>
#include <cuda_bf16.h>
#include <cuda_fp16.h>
#include <cstdint>

// CausalSelfAttention: B=4, T=4096, C=128, fp32 in/out.
// K1: tensorized QKV projection, fp16 2-term GEMM (x fp16 hi/lo x W fp16).
//     Outputs: Q fp16 (pre-scaled), K fp16, V fp16 (transposed).
// K2: persistent flash attention: warp-private 16-row tiles; S,PV fp16
//     single-term; masked warp-tile skip (static traversal order — runtime
//     index stagger removed: it demoted accumulator arrays to local memory);
//     cp.async staged Q + double-buffered K/V; split-KV queue; fused combine.

#define BB 4
#define TT 4096
#define CC 128
#define BT (BB*TT)
#define QT_N 32
#define SCALE_L2E (0.08838834764831845f * 1.4426950408889634f)

#define BQ 128
#define BKT 64
#define CH 6
#define MAXSUB 11
#define NSLICES 748     // 4 * sum_qt ceil((2qt+2)/6)
#define NCTA 148

// ---------------- scratch (device globals; no cudaMalloc) -------------------
__device__ __align__(256) __half g_q[BT*CC];                 // [t][c] fp16, *SCALE_L2E
__device__ __align__(256) __half g_k[BT*CC];                 // [t][c] fp16
__device__ __align__(256) __half g_v[BB*CC*TT];              // [b][c][t] fp16
__device__ __align__(256) float g_po[BB*QT_N*MAXSUB][BQ*CC];
__device__ __align__(256) float g_pl[BB*QT_N*MAXSUB][BQ];
__device__ int g_ctr;
__device__ int g_done[BB*QT_N];

// ---------------- helpers ---------------------------------------------------
__device__ __forceinline__ uint32_t smem_u32(const void* p) {
    uint32_t a;
    asm("{ .reg .u64 t; cvta.to.shared.u64 t, %1; cvt.u32.u64 %0, t; }"
        : "=r"(a) : "l"(p));
    return a;
}
__device__ __forceinline__ void ldm4(uint32_t* r, uint32_t a) {
    asm volatile("ldmatrix.sync.aligned.m8n8.x4.shared.b16 {%0,%1,%2,%3}, [%4];"
        : "=r"(r[0]), "=r"(r[1]), "=r"(r[2]), "=r"(r[3]) : "r"(a));
}
__device__ __forceinline__ void mma16816h(float* c, const uint32_t* a,
                                          const uint32_t* b) {
    asm("mma.sync.aligned.m16n8k16.row.col.f32.f16.f16.f32 "
        "{%0,%1,%2,%3}, {%4,%5,%6,%7}, {%8,%9}, {%0,%1,%2,%3};"
        : "+f"(c[0]), "+f"(c[1]), "+f"(c[2]), "+f"(c[3])
        : "r"(a[0]), "r"(a[1]), "r"(a[2]), "r"(a[3]), "r"(b[0]), "r"(b[1]));
}
#define CP_ASYNC16(dst, src) \
    asm volatile("cp.async.cg.shared.global [%0], [%1], 16;" \
                 :: "r"(dst), "l"(src))
#define CP_COMMIT() asm volatile("cp.async.commit_group;" ::: "memory")
#define CP_WAIT(n)  asm volatile("cp.async.wait_group %0;" :: "n"(n) : "memory")

// ---------------------------------------------------------------------------
// K1: QKV projection, fp16 2-term: y = xh*W + xl*W.
// ---------------------------------------------------------------------------
#define PX 136
#define SMX_H 0
#define SMX_L (SMX_H + 128*PX*2)
#define SMW   (SMX_L + 128*PX*2)
#define PROJ_SMEM (SMW + 128*PX*2)      // 104448
#define PSTG 129

__global__ __launch_bounds__(256, 1) void qkv_proj_mma(
    const float* __restrict__ x,
    const float* __restrict__ Wq,
    const float* __restrict__ Wk,
    const float* __restrict__ Wv)
{
    extern __shared__ char smem[];
    const uint32_t sb = smem_u32(smem);
    const int widx = blockIdx.y;
    const float* __restrict__ W = (widx == 0) ? Wq : ((widx == 1) ? Wk : Wv);
    const int row0 = blockIdx.x * 128;
    const int tid = threadIdx.x, lane = tid & 31, wid = tid >> 5;
    const int wm = wid & 3, wn = wid >> 2;
    const int gr = lane >> 2, tc = lane & 3;

    if (blockIdx.x == 0 && widx == 0) {
        if (tid == 0) g_ctr = NCTA;
        if (tid < BB * QT_N) g_done[tid] = 0;
    }

    // x: split to fp16 hi/lo
#pragma unroll
    for (int f = tid; f < 128 * 32; f += 256) {
        const int r = f >> 5, c4 = (f & 31) * 4;
        float4 v = *(const float4*)&x[(size_t)(row0 + r) * CC + c4];
        __half2 h0 = __floats2half2_rn(v.x, v.y);
        __half2 h1 = __floats2half2_rn(v.z, v.w);
        __half2 l0 = __floats2half2_rn(v.x - __low2float(h0),
                                       v.y - __high2float(h0));
        __half2 l1 = __floats2half2_rn(v.z - __low2float(h1),
                                       v.w - __high2float(h1));
        const int o = (r * PX + c4) * 2;
        *(uint32_t*)(smem + SMX_H + o)     = *reinterpret_cast<uint32_t*>(&h0);
        *(uint32_t*)(smem + SMX_H + o + 4) = *reinterpret_cast<uint32_t*>(&h1);
        *(uint32_t*)(smem + SMX_L + o)     = *reinterpret_cast<uint32_t*>(&l0);
        *(uint32_t*)(smem + SMX_L + o + 4) = *reinterpret_cast<uint32_t*>(&l1);
    }
    // W: single fp16
#pragma unroll
    for (int f = tid; f < 128 * 32; f += 256) {
        const int d = f >> 5, c4 = (f & 31) * 4;
        float4 v = *(const float4*)&W[(size_t)d * CC + c4];
        __half2 h0 = __floats2half2_rn(v.x, v.y);
        __half2 h1 = __floats2half2_rn(v.z, v.w);
        const int o = (d * PX + c4) * 2;
        *(uint32_t*)(smem + SMW + o)     = *reinterpret_cast<uint32_t*>(&h0);
        *(uint32_t*)(smem + SMW + o + 4) = *reinterpret_cast<uint32_t*>(&h1);
    }
    __syncthreads();

    const int lr = lane & 15, lh = lane >> 4;
    const int bn = (lane & 7) + ((lane >> 4) << 3);
    const int bk8 = ((lane >> 3) & 1) << 3;
    const uint32_t aXh = sb + SMX_H + (((wm * 32 + lr) * PX) + lh * 8) * 2;
    const uint32_t aXl = aXh + (SMX_L - SMX_H);
    const uint32_t aW  = sb + SMW + (((wn * 64 + bn) * PX) + bk8) * 2;

    float acc[2][8][4];
#pragma unroll
    for (int mi = 0; mi < 2; mi++)
#pragma unroll
        for (int ni = 0; ni < 8; ni++)
#pragma unroll
            for (int e = 0; e < 4; e++) acc[mi][ni][e] = 0.0f;

#pragma unroll
    for (int ks = 0; ks < 8; ++ks) {
        uint32_t ah[2][4], al[2][4], bw[8][2];
        ldm4(ah[0], aXh + ks * 32);
        ldm4(ah[1], aXh + 16 * PX * 2 + ks * 32);
        ldm4(al[0], aXl + ks * 32);
        ldm4(al[1], aXl + 16 * PX * 2 + ks * 32);
#pragma unroll
        for (int p = 0; p < 4; p++)
            ldm4(&bw[2 * p][0], aW + p * 16 * PX * 2 + ks * 32);
#pragma unroll
        for (int mi = 0; mi < 2; mi++)
#pragma unroll
            for (int ni = 0; ni < 8; ni++) {
                mma16816h(acc[mi][ni], ah[mi], bw[ni]);
                mma16816h(acc[mi][ni], al[mi], bw[ni]);
            }
    }

    if (widx < 2) {
        // ---- Q (scaled) / K: single fp16, row-major ----
        __half* dst = (widx == 0) ? g_q : g_k;
        const float sc = (widx == 0) ? SCALE_L2E : 1.0f;
#pragma unroll
        for (int mi = 0; mi < 2; mi++)
#pragma unroll
            for (int half = 0; half < 2; half++) {
                const int row = wm * 32 + mi * 16 + gr + half * 8;
                const size_t rb = (size_t)(row0 + row) * CC;
#pragma unroll
                for (int ni = 0; ni < 8; ni++) {
                    const int col = wn * 64 + ni * 8 + tc * 2;
                    __half2 H = __floats2half2_rn(acc[mi][ni][half * 2 + 0] * sc,
                                                  acc[mi][ni][half * 2 + 1] * sc);
                    *(uint32_t*)&dst[rb + col] = *reinterpret_cast<uint32_t*>(&H);
                }
            }
    } else {
        // ---- V: stage fp32, transposed single-fp16 store ----
        __syncthreads();
        float* stg = (float*)smem;
#pragma unroll
        for (int mi = 0; mi < 2; mi++)
#pragma unroll
            for (int half = 0; half < 2; half++) {
                const int row = wm * 32 + mi * 16 + gr + half * 8;
#pragma unroll
                for (int ni = 0; ni < 8; ni++) {
                    const int col = wn * 64 + ni * 8 + tc * 2;
                    stg[row * PSTG + col]     = acc[mi][ni][half * 2 + 0];
                    stg[row * PSTG + col + 1] = acc[mi][ni][half * 2 + 1];
                }
            }
        __syncthreads();
        const int b = row0 >> 12, t0 = row0 & (TT - 1);
        __half* vv = g_v + (size_t)b * CC * TT + t0;
#pragma unroll 1
        for (int c = wid; c < 128; c += 8) {
            float v[4];
#pragma unroll
            for (int i = 0; i < 4; i++)
                v[i] = stg[(lane * 4 + i) * PSTG + c];
            __half2 h0 = __floats2half2_rn(v[0], v[1]);
            __half2 h1 = __floats2half2_rn(v[2], v[3]);
            uint2 Hp = make_uint2(*reinterpret_cast<uint32_t*>(&h0),
                                  *reinterpret_cast<uint32_t*>(&h1));
            *(uint2*)&vv[(size_t)c * TT + lane * 4] = Hp;
        }
    }
}

// ---------------------------------------------------------------------------
// K2: persistent flash attention + fused combine. Q/K/V all single fp16.
// ---------------------------------------------------------------------------
#define PQ 136
#define PK 136
#define PV 72
#define SM_Q 0
#define SM_KV (128*PQ*2)                 // 34816
#define KBUF  (64*PK*2)                  // 17408
#define OFF_K 0
#define OFF_V KBUF
#define BUFSZ (KBUF + 128*PV*2)          // 35840
#define SM_NEXT (SM_KV + 2*BUFSZ)        // +0 next, +4 flag
#define SM_INVL (SM_NEXT + 16)
#define FLASH_SMEM (SM_INVL + 128*4)

__device__ __forceinline__ void prefetch_kv(uint32_t buf, int b, int j, int tid)
{
    const __half* kk = g_k + (size_t)(b * TT + j * BKT) * CC;
#pragma unroll
    for (int u = 0; u < 4; u++) {
        const int f = tid + u * 256, r = f >> 4, c8 = (f & 15) << 3;
        CP_ASYNC16(buf + OFF_K + (r * PK + c8) * 2, kk + r * CC + c8);
    }
    const __half* vv = g_v + (size_t)b * CC * TT + j * BKT;
#pragma unroll
    for (int u = 0; u < 4; u++) {
        const int f = tid + u * 256, d = f >> 3, c8 = (f & 7) << 3;
        CP_ASYNC16(buf + OFF_V + (d * PV + c8) * 2, vv + (size_t)d * TT + c8);
    }
}

__global__ __launch_bounds__(256, 1) void flash_attn(float* __restrict__ out)
{
    extern __shared__ char smem[];
    const uint32_t sb = smem_u32(smem);
    const int tid = threadIdx.x, lane = tid & 31, wid = tid >> 5;
    const int gr = lane >> 2, tc = lane & 3;

    const int lr = lane & 15, lh = lane >> 4;
    const int bn = (lane & 7) + ((lane >> 4) << 3);
    const int bk8 = ((lane >> 3) & 1) << 3;

    const uint32_t aQ = sb + SM_Q + (((wid * 16 + lr) * PQ) + lh * 8) * 2;
    const uint32_t aKrel = (bn * PK + bk8) * 2;
    const uint32_t aVrel = (bn * PV + bk8) * 2;

    const int row_a = wid * 16 + gr;
    const int row_b = row_a + 8;
    const int row_max = wid * 16 + 15;   // warp's max q row (for tile skip)
    int* s_next = (int*)(smem + SM_NEXT);
    int* s_flag = (int*)(smem + SM_NEXT + 4);

    int slice = blockIdx.x;
    while (slice < NSLICES) {
        // ---- decode slice -> (b, qt, sub, kv0, kv1, ns) ----
        int rem = slice, qt = 31, ns = 1;
#pragma unroll 1
        for (qt = 31; qt > 0; --qt) {
            ns = (2 * qt + 2 + CH - 1) / CH;
            if (rem < 4 * ns) break;
            rem -= 4 * ns;
        }
        if (qt == 0) ns = 1;
        const int b = rem & 3, sub = rem >> 2;
        const int it = 2 * qt + 2;
        const int base = it / ns, r2 = it - base * ns;
        const int kv0 = sub * base + (sub < r2 ? sub : r2);
        const int kv1 = kv0 + base + (sub < r2 ? 1 : 0);
        const int slot = (b * QT_N + qt) * MAXSUB + sub;

        // ---- prologue: cp.async Q (group 1) then KV0 (group 2) ----
        {
            const __half* qq = g_q + (size_t)(b * TT + qt * BQ) * CC;
#pragma unroll
            for (int u = 0; u < 8; u++) {
                const int f = tid + u * 256, r = f >> 4, c8 = (f & 15) << 3;
                CP_ASYNC16(sb + SM_Q + (r * PQ + c8) * 2, qq + r * CC + c8);
            }
        }
        CP_COMMIT();
        prefetch_kv(sb + SM_KV, b, kv0, tid);
        CP_COMMIT();
        CP_WAIT(1);                      // Q complete; KV0 may be in flight
        __syncthreads();                 // Q visible to all warps
        uint32_t qah[8][4];
#pragma unroll
        for (int ks = 0; ks < 8; ++ks)
            ldm4(qah[ks], aQ + ks * 32);

        float o[16][4];
#pragma unroll
        for (int ni = 0; ni < 16; ni++)
#pragma unroll
            for (int e = 0; e < 4; e++) o[ni][e] = 0.0f;
        float lsumA = 0.0f, lsumB = 0.0f;

        int cur = 0;
#pragma unroll 1
        for (int j = kv0; j < kv1; ++j, cur ^= 1) {
            __syncthreads();             // prev-buffer reads complete
            if (j + 1 < kv1) {
                prefetch_kv(sb + SM_KV + (cur ^ 1) * BUFSZ, b, j + 1, tid);
                CP_COMMIT();
                CP_WAIT(1);              // tile j complete, j+1 in flight
            } else {
                CP_WAIT(0);
            }
            __syncthreads();             // tile j visible

            const int srel = j * BKT - qt * BQ;
            if (srel > row_max) continue;    // warp-tile fully masked

            const uint32_t kb = sb + SM_KV + cur * BUFSZ;
            const uint32_t aK = kb + OFF_K + aKrel;
            const uint32_t aV = kb + OFF_V + aVrel;

            // ---- S = Q K^T (16x64), fp16 single-term ----
            float s[8][4];
#pragma unroll
            for (int ni = 0; ni < 8; ni++)
#pragma unroll
                for (int e = 0; e < 4; e++) s[ni][e] = 0.0f;

#pragma unroll
            for (int ks = 0; ks < 8; ++ks) {
#pragma unroll
                for (int p = 0; p < 4; p++) {
                    uint32_t k4[4];
                    ldm4(k4, aK + p * 16 * PK * 2 + ks * 32);
                    mma16816h(s[2 * p],     qah[ks], &k4[0]);
                    mma16816h(s[2 * p + 1], qah[ks], &k4[2]);
                }
            }

            // ---- softmax -> fp16 Ph A-fragments; l over rounded Ph ----
            uint32_t ph[4][4];
            if (srel + BKT - 1 <= row_a) {
                // fully unmasked for this warp's rows: no compares
#pragma unroll
                for (int ni = 0; ni < 8; ni++) {
                    const int ksv = ni >> 1, hh = (ni & 1) * 2;
                    float p0 = exp2f(s[ni][0]);
                    float p1 = exp2f(s[ni][1]);
                    float p2 = exp2f(s[ni][2]);
                    float p3 = exp2f(s[ni][3]);
                    __half2 H0 = __floats2half2_rn(p0, p1);
                    __half2 H1 = __floats2half2_rn(p2, p3);
                    lsumA += __low2float(H0) + __high2float(H0);
                    lsumB += __low2float(H1) + __high2float(H1);
                    ph[ksv][hh]     = *reinterpret_cast<uint32_t*>(&H0);
                    ph[ksv][hh + 1] = *reinterpret_cast<uint32_t*>(&H1);
                }
            } else {
#pragma unroll
                for (int ni = 0; ni < 8; ni++) {
                    const int ksv = ni >> 1, hh = (ni & 1) * 2;
                    const int col = srel + ni * 8 + tc * 2;
                    float p0 = (col     <= row_a) ? exp2f(s[ni][0]) : 0.0f;
                    float p1 = (col + 1 <= row_a) ? exp2f(s[ni][1]) : 0.0f;
                    float p2 = (col     <= row_b) ? exp2f(s[ni][2]) : 0.0f;
                    float p3 = (col + 1 <= row_b) ? exp2f(s[ni][3]) : 0.0f;
                    __half2 H0 = __floats2half2_rn(p0, p1);
                    __half2 H1 = __floats2half2_rn(p2, p3);
                    lsumA += __low2float(H0) + __high2float(H0);
                    lsumB += __low2float(H1) + __high2float(H1);
                    ph[ksv][hh]     = *reinterpret_cast<uint32_t*>(&H0);
                    ph[ksv][hh + 1] = *reinterpret_cast<uint32_t*>(&H1);
                }
            }

            // ---- O += P V (16x128), fp16, single-V ----
#pragma unroll
            for (int ksv = 0; ksv < 4; ++ksv) {
#pragma unroll
                for (int p = 0; p < 8; p++) {
                    uint32_t v4[4];
                    ldm4(v4, aV + p * 16 * PV * 2 + ksv * 32);
                    mma16816h(o[2 * p],     ph[ksv], &v4[0]);
                    mma16816h(o[2 * p + 1], ph[ksv], &v4[2]);
                }
            }
        }

        // ---- slice epilogue: l reduce + partial writes ----
        lsumA += __shfl_xor_sync(0xffffffffu, lsumA, 1);
        lsumA += __shfl_xor_sync(0xffffffffu, lsumA, 2);
        lsumB += __shfl_xor_sync(0xffffffffu, lsumB, 1);
        lsumB += __shfl_xor_sync(0xffffffffu, lsumB, 2);
        if (tc == 0) {
            g_pl[slot][row_a] = lsumA;
            g_pl[slot][row_b] = lsumB;
        }
        float* po = g_po[slot];
#pragma unroll
        for (int ni = 0; ni < 16; ni++) {
            const int col = ni * 8 + tc * 2;
            *(float2*)&po[row_a * CC + col] = make_float2(o[ni][0], o[ni][1]);
            *(float2*)&po[row_b * CC + col] = make_float2(o[ni][2], o[ni][3]);
        }

        // ---- fused combine: last-arriving CTA for this (b,qt) finishes it ----
        __threadfence();
        __syncthreads();
        if (tid == 0) {
            int old = atomicAdd(&g_done[b * QT_N + qt], 1);
            *s_flag = (old == ns - 1) ? 1 : 0;
        }
        __syncthreads();
        if (*s_flag) {
            __threadfence();
            const int s0 = (b * QT_N + qt) * MAXSUB;
            float* invl = (float*)(smem + SM_INVL);
            for (int r = tid; r < 128; r += 256) {
                float ssum = 0.0f;
                for (int u = 0; u < ns; u++) ssum += g_pl[s0 + u][r];
                invl[r] = 1.0f / ssum;
            }
            __syncthreads();
            float* dst = out + (size_t)(b * TT + qt * BQ) * CC;
#pragma unroll 2
            for (int f = tid; f < BQ * CC / 4; f += 256) {
                const int row = f >> 5;
                float4 a = *(const float4*)&g_po[s0][f * 4];
                for (int u = 1; u < ns; u++) {
                    float4 v = *(const float4*)&g_po[s0 + u][f * 4];
                    a.x += v.x; a.y += v.y; a.z += v.z; a.w += v.w;
                }
                const float inv = invl[row];
                a.x *= inv; a.y *= inv; a.z *= inv; a.w *= inv;
                *(float4*)&dst[f * 4] = a;
            }
        }

        // ---- pop next slice ----
        if (tid == 0) *s_next = atomicAdd(&g_ctr, 1);
        __syncthreads();
        slice = *s_next;
    }
}

// ---------------------------------------------------------------------------
extern "C" void kernel_launch(void* const* d_in, const int* in_sizes, int n_in,
                              void* d_out, int out_size)
{
    const float* x  = (const float*)d_in[0];
    const float* Wq = (const float*)d_in[1];
    const float* Wk = (const float*)d_in[2];
    const float* Wv = (const float*)d_in[3];
    float* out = (float*)d_out;

    cudaFuncSetAttribute(flash_attn,
                         cudaFuncAttributeMaxDynamicSharedMemorySize,
                         FLASH_SMEM);
    cudaFuncSetAttribute(qkv_proj_mma,
                         cudaFuncAttributeMaxDynamicSharedMemorySize,
                         PROJ_SMEM);

    qkv_proj_mma<<<dim3(BT / 128, 3), 256, PROJ_SMEM>>>(x, Wq, Wk, Wv);
    flash_attn<<<NCTA, 256, FLASH_SMEM>>>(out);
}